// round 3
// baseline (speedup 1.0000x reference)
#include <cuda_runtime.h>

#define BD 4
#define TD 32
#define HD 224
#define WD 224
#define CD 3
#define NPIXELS (BD*TD*HD*WD)   // 6,422,528
#define N1 79                   // int(6422528*0.2*0.8 // 13005)
#define N2 9                    // int(6422528*0.2*0.1 // 13005)
#define NBOX (N1 + 2*N2)        // 97

#define PAINT_SPLIT 4           // blocks per box

// Paint one class of boxes into out. use_random=0 -> mask_token, 1 -> frames[r*]
__global__ void paint_kernel(const int* __restrict__ b, const int* __restrict__ t,
                             const int* __restrict__ h, const int* __restrict__ w,
                             int box_off,
                             const float* __restrict__ mask_token,
                             const float* __restrict__ frames,
                             const int* __restrict__ rb, const int* __restrict__ rt,
                             const int* __restrict__ rh, const int* __restrict__ rw,
                             int use_random,
                             float* __restrict__ out) {
    int box  = box_off + (blockIdx.x / PAINT_SPLIT);
    int part = blockIdx.x % PAINT_SPLIT;

    float tok0, tok1, tok2;
    if (use_random) {
        long long ridx = ((((long long)rb[0] * TD + rt[0]) * HD + rh[0]) * WD + rw[0]) * CD;
        tok0 = __ldg(frames + ridx + 0);
        tok1 = __ldg(frames + ridx + 1);
        tok2 = __ldg(frames + ridx + 2);
    } else {
        tok0 = __ldg(mask_token + 0);
        tok1 = __ldg(mask_token + 1);
        tok2 = __ldg(mask_token + 2);
    }

    int bi = b[box], ti = t[box], hi0 = h[box], wi = w[box];
    int tlo = max(ti - 2, 0),   thi = min(ti + 2, TD - 1);
    int hlo = max(hi0 - 25, 0), hhi = min(hi0 + 25, HD - 1);
    int wlo = max(wi - 25, 0),  whi = min(wi + 25, WD - 1);

    int nh = hhi - hlo;
    int nt = thi - tlo;
    int nwf = (whi - wlo) * CD;          // floats per row segment
    int nrows = nt * nh;
    int total = nrows * nwf;

    for (int e = part * blockDim.x + threadIdx.x; e < total;
         e += PAINT_SPLIT * blockDim.x) {
        int row = e / nwf;
        int rem = e - row * nwf;
        int tt = tlo + row / nh;
        int hh = hlo + row - (row / nh) * nh;
        long long addr = ((((long long)bi * TD + tt) * HD + hh) * WD + wlo) * CD + rem;
        int c = rem % CD;
        out[addr] = (c == 0) ? tok0 : (c == 1) ? tok1 : tok2;
    }
}

// One block: compute M[b,t] exactly from all 97 boxes' (b, t-range).
// Every box has a non-empty h/w footprint, so interval membership == pixel union.
__global__ void mvis_kernel(const int* __restrict__ b, const int* __restrict__ t,
                            float* __restrict__ M_out) {
    int bt = threadIdx.x;               // 0..127
    if (bt >= BD * TD) return;
    int bb = bt / TD, tt = bt % TD;
    float m = 0.0f;
    #pragma unroll 1
    for (int i = 0; i < NBOX; i++) {
        int bi = b[i], ti = t[i];
        int tlo = max(ti - 2, 0), thi = min(ti + 2, TD - 1);
        if (bi == bb && tt >= tlo && tt < thi) m = 1.0f;
    }
    M_out[bt] = m;
}

extern "C" void kernel_launch(void* const* d_in, const int* in_sizes, int n_in,
                              void* d_out, int out_size) {
    const float* frames     = (const float*)d_in[0];
    const float* mask_token = (const float*)d_in[1];
    const int* b  = (const int*)d_in[2];
    const int* t  = (const int*)d_in[3];
    const int* h  = (const int*)d_in[4];
    const int* w  = (const int*)d_in[5];
    const int* rb = (const int*)d_in[6];
    const int* rt = (const int*)d_in[7];
    const int* rh = (const int*)d_in[8];
    const int* rw = (const int*)d_in[9];

    float* out = (float*)d_out;
    float* M_out = out + (size_t)NPIXELS * CD;

    // 1) bulk copy frames -> out (driver-optimized D2D, no dependencies)
    cudaMemcpyAsync(out, frames, (size_t)NPIXELS * CD * sizeof(float),
                    cudaMemcpyDeviceToDevice);

    // 2) paint R1 (mask_token), then R2 (random_token) — order gives R2-wins
    paint_kernel<<<N1 * PAINT_SPLIT, 256>>>(b, t, h, w, 0, mask_token,
                                            frames, rb, rt, rh, rw, 0, out);
    paint_kernel<<<N2 * PAINT_SPLIT, 256>>>(b, t, h, w, N1, mask_token,
                                            frames, rb, rt, rh, rw, 1, out);

    // 3) visibility mask M[4,32]
    mvis_kernel<<<1, 128>>>(b, t, M_out);
}

// round 5
// speedup vs baseline: 1.8139x; 1.8139x over previous
#include <cuda_runtime.h>

#define BD 4
#define TD 32
#define HD 224
#define WD 224
#define CD 3
#define NPIXELS (BD*TD*HD*WD)   // 6,422,528
#define N1 79
#define N2 9
#define NPAINT (N1 + N2)        // 88
#define NBOX (N1 + 2*N2)        // 97

#define ROWS_PER_BLK 4
#define NROWS (BD*TD*HD)        // 28,672
#define NBLK (NROWS / ROWS_PER_BLK)  // 7,168
#define TPB 224                 // 224 threads * 4 px = 896 px = 4 rows

__global__ void __launch_bounds__(TPB) fused_kernel(
    const float* __restrict__ frames, const float* __restrict__ mask_token,
    const int* __restrict__ b, const int* __restrict__ t,
    const int* __restrict__ h, const int* __restrict__ w,
    const int* __restrict__ rb, const int* __restrict__ rt,
    const int* __restrict__ rh, const int* __restrict__ rw,
    float* __restrict__ out, float* __restrict__ M_out)
{
    // ---- tail block: visibility mask M[b,t] ----
    if (blockIdx.x == NBLK) {
        int bt = threadIdx.x;
        if (bt < BD * TD) {
            int bb = bt / TD, tt = bt % TD;
            float m = 0.0f;
            for (int i = 0; i < NBOX; i++) {
                int tlo = max(t[i] - 2, 0), thi = min(t[i] + 2, TD - 1);
                if (b[i] == bb && tt >= tlo && tt < thi) m = 1.0f;
            }
            M_out[bt] = m;
        }
        return;
    }

    __shared__ int s_n;
    __shared__ int s_hlo[NPAINT], s_hhi[NPAINT], s_wlo[NPAINT], s_whi[NPAINT];
    __shared__ unsigned char s_bit[NPAINT];

    int r0 = blockIdx.x * ROWS_PER_BLK;   // first global row (b,t,h triple)
    int h0 = r0 % HD;
    int bt = r0 / HD;
    int tt = bt % TD, bb = bt / TD;

    if (threadIdx.x == 0) s_n = 0;
    __syncthreads();

    // box culling against this block's (b, t, [h0, h0+4))
    if (threadIdx.x < NPAINT) {
        int i = threadIdx.x;
        int ti = __ldg(t + i);
        int tlo = max(ti - 2, 0), thi = min(ti + 2, TD - 1);
        if (__ldg(b + i) == bb && tt >= tlo && tt < thi) {
            int hi = __ldg(h + i);
            int hlo = max(hi - 25, 0), hhi = min(hi + 25, HD - 1);
            if (hlo < h0 + ROWS_PER_BLK && hhi > h0) {
                int slot = atomicAdd(&s_n, 1);
                int wi = __ldg(w + i);
                s_hlo[slot] = hlo;
                s_hhi[slot] = hhi;
                s_wlo[slot] = max(wi - 25, 0);
                s_whi[slot] = min(wi + 25, WD - 1);
                s_bit[slot] = (i < N1) ? 1 : 2;
            }
        }
    }
    __syncthreads();
    int ncov = s_n;

    // thread's 4 pixels: contiguous, within one row
    int p  = threadIdx.x * 4;             // pixel offset in block (0..895)
    int f4idx = r0 * 168 + threadIdx.x * 3;   // float4 index (row = 672 floats = 168 f4)
    const float4* src = reinterpret_cast<const float4*>(frames) + f4idx;
    float4* dst = reinterpret_cast<float4*>(out) + f4idx;

    float4 a = src[0], q = src[1], c = src[2];

    if (ncov > 0) {
        int hh = h0 + p / WD;
        int w0 = p % WD;
        unsigned int f = 0;               // 2 bits per pixel: [r2r1][r2r1]...
        for (int s = 0; s < ncov; s++) {
            if (hh >= s_hlo[s] && hh < s_hhi[s]) {
                int wlo = s_wlo[s], whi = s_whi[s];
                unsigned int bit = s_bit[s];
                #pragma unroll
                for (int j = 0; j < 4; j++) {
                    int ww = w0 + j;
                    if (ww >= wlo && ww < whi) f |= bit << (j * 2);
                }
            }
        }
        if (f != 0u) {
            float mt0 = __ldg(mask_token + 0), mt1 = __ldg(mask_token + 1), mt2 = __ldg(mask_token + 2);
            long long ridx = ((((long long)__ldg(rb) * TD + __ldg(rt)) * HD + __ldg(rh)) * WD + __ldg(rw)) * CD;
            float rt0 = __ldg(frames + ridx), rt1 = __ldg(frames + ridx + 1), rt2 = __ldg(frames + ridx + 2);

            float v[12];
            v[0]=a.x; v[1]=a.y; v[2]=a.z; v[3]=a.w;
            v[4]=q.x; v[5]=q.y; v[6]=q.z; v[7]=q.w;
            v[8]=c.x; v[9]=c.y; v[10]=c.z; v[11]=c.w;
            #pragma unroll
            for (int j = 0; j < 4; j++) {
                unsigned int fj = (f >> (j * 2)) & 3u;
                if (fj) {
                    bool r2 = (fj & 2u) != 0u;   // R2 wins over R1
                    v[j*3+0] = r2 ? rt0 : mt0;
                    v[j*3+1] = r2 ? rt1 : mt1;
                    v[j*3+2] = r2 ? rt2 : mt2;
                }
            }
            a.x=v[0]; a.y=v[1]; a.z=v[2]; a.w=v[3];
            q.x=v[4]; q.y=v[5]; q.z=v[6]; q.w=v[7];
            c.x=v[8]; c.y=v[9]; c.z=v[10]; c.w=v[11];
        }
    }

    dst[0] = a; dst[1] = q; dst[2] = c;
}

extern "C" void kernel_launch(void* const* d_in, const int* in_sizes, int n_in,
                              void* d_out, int out_size) {
    const float* frames     = (const float*)d_in[0];
    const float* mask_token = (const float*)d_in[1];
    const int* b  = (const int*)d_in[2];
    const int* t  = (const int*)d_in[3];
    const int* h  = (const int*)d_in[4];
    const int* w  = (const int*)d_in[5];
    const int* rb = (const int*)d_in[6];
    const int* rt = (const int*)d_in[7];
    const int* rh = (const int*)d_in[8];
    const int* rw = (const int*)d_in[9];

    float* out = (float*)d_out;
    float* M_out = out + (size_t)NPIXELS * CD;

    fused_kernel<<<NBLK + 1, TPB>>>(frames, mask_token, b, t, h, w,
                                    rb, rt, rh, rw, out, M_out);
}